// round 1
// baseline (speedup 1.0000x reference)
#include <cuda_runtime.h>
#include <math.h>

#define PP 1024
#define LL 32
#define EE 512
#define DD 768
#define NLAY 6
#define FFD 3072
#define TT (PP*LL)   // 32768 byte tokens

// ---------------- scratch (static device globals; no runtime alloc) ----------------
__device__ float g_emb[TT*EE];          // 64 MB
__device__ float g_qkv[TT*3*EE];        // 192 MB
__device__ float g_attn[TT*EE];         // 64 MB
__device__ float g_attnout[TT*EE];      // 64 MB
__device__ float g_patch[PP*EE];
__device__ float g_h[PP*DD];
__device__ float g_hn[PP*DD];
__device__ float g_qkvt[PP*3*DD];
__device__ float g_scores[8*PP*PP];     // 33.5 MB
__device__ float g_attnt[PP*DD];
__device__ float g_ff[PP*FFD];

// ---------------- block reductions ----------------
__device__ __forceinline__ float blockSum(float v){
    __shared__ float sh[32];
    int lane = threadIdx.x & 31, wid = threadIdx.x >> 5, nw = blockDim.x >> 5;
    #pragma unroll
    for (int o = 16; o; o >>= 1) v += __shfl_xor_sync(0xffffffffu, v, o);
    if (lane == 0) sh[wid] = v;
    __syncthreads();
    float t = (lane < nw) ? sh[lane] : 0.f;
    #pragma unroll
    for (int o = 16; o; o >>= 1) t += __shfl_xor_sync(0xffffffffu, t, o);
    __syncthreads();
    return t;
}
__device__ __forceinline__ float blockMax(float v){
    __shared__ float sh[32];
    int lane = threadIdx.x & 31, wid = threadIdx.x >> 5, nw = blockDim.x >> 5;
    #pragma unroll
    for (int o = 16; o; o >>= 1) v = fmaxf(v, __shfl_xor_sync(0xffffffffu, v, o));
    if (lane == 0) sh[wid] = v;
    __syncthreads();
    float t = (lane < nw) ? sh[lane] : -1e30f;
    #pragma unroll
    for (int o = 16; o; o >>= 1) t = fmaxf(t, __shfl_xor_sync(0xffffffffu, t, o));
    __syncthreads();
    return t;
}

// ---------------- embedding + mask ----------------
__global__ void embed_kernel(const int* __restrict__ tokens, const int* __restrict__ lengths,
                             const float* __restrict__ bemb, const float* __restrict__ lpos,
                             float* __restrict__ out){
    int idx = blockIdx.x * blockDim.x + threadIdx.x;
    if (idx >= TT * EE) return;
    int e = idx & (EE - 1);
    int t = idx >> 9;          // token index (EE=512)
    int l = t & (LL - 1);
    int p = t >> 5;
    float v = 0.f;
    if (l < lengths[p]) {
        int tok = tokens[t];
        v = bemb[tok * EE + e] + lpos[l * EE + e];
    }
    out[idx] = v;
}

// ---------------- generic strided/batched SGEMM: C = A[M,K] * B[N,K]^T (+epi) ----------------
// epi: 0 none, 1 bias, 2 bias+gelu(exact), 3 bias+residual
template<int BM, int BN, int BK, int TM, int TN>
__global__ void gemm_kernel(const float* __restrict__ A, const float* __restrict__ B,
                            const float* __restrict__ bias, const float* __restrict__ res,
                            float* __restrict__ C,
                            int M, int N, int K,
                            int lda_m, int lda_k, int ldb_n, int ldb_k, int ldc,
                            long long bA, long long bB, long long bC, int epi){
    constexpr int PAD = 4;
    constexpr int NT  = (BM / TM) * (BN / TN);   // 256
    __shared__ float As[BK][BM + PAD];
    __shared__ float Bs[BK][BN + PAD];
    const int tid = threadIdx.x;
    A += (long long)blockIdx.z * bA;
    B += (long long)blockIdx.z * bB;
    C += (long long)blockIdx.z * bC;
    const int m0 = blockIdx.y * BM, n0 = blockIdx.x * BN;
    const int tx = tid % (BN / TN), ty = tid / (BN / TN);
    float acc[TM][TN];
    #pragma unroll
    for (int i = 0; i < TM; i++)
        #pragma unroll
        for (int j = 0; j < TN; j++) acc[i][j] = 0.f;

    constexpr int AELEM = BM * BK / NT;
    constexpr int BELEM = BN * BK / NT;

    for (int k0 = 0; k0 < K; k0 += BK) {
        if (lda_k == 1) {
            #pragma unroll
            for (int i = 0; i < AELEM; i++) {
                int idx = i * NT + tid; int m = idx / BK, kk = idx % BK;
                int gm = m0 + m, gk = k0 + kk;
                As[kk][m] = (gm < M && gk < K) ? A[(long long)gm * lda_m + gk] : 0.f;
            }
        } else {
            #pragma unroll
            for (int i = 0; i < AELEM; i++) {
                int idx = i * NT + tid; int m = idx % BM, kk = idx / BM;
                int gm = m0 + m, gk = k0 + kk;
                As[kk][m] = (gm < M && gk < K) ? A[(long long)gm * lda_m + (long long)gk * lda_k] : 0.f;
            }
        }
        if (ldb_k == 1) {
            #pragma unroll
            for (int i = 0; i < BELEM; i++) {
                int idx = i * NT + tid; int n = idx / BK, kk = idx % BK;
                int gn = n0 + n, gk = k0 + kk;
                Bs[kk][n] = (gn < N && gk < K) ? B[(long long)gn * ldb_n + gk] : 0.f;
            }
        } else {
            #pragma unroll
            for (int i = 0; i < BELEM; i++) {
                int idx = i * NT + tid; int n = idx % BN, kk = idx / BN;
                int gn = n0 + n, gk = k0 + kk;
                Bs[kk][n] = (gn < N && gk < K) ? B[(long long)gn * ldb_n + (long long)gk * ldb_k] : 0.f;
            }
        }
        __syncthreads();
        #pragma unroll
        for (int kk = 0; kk < BK; kk++) {
            float ar[TM], br[TN];
            #pragma unroll
            for (int i = 0; i < TM / 4; i++) {
                float4 t = *(const float4*)&As[kk][ty * TM + i * 4];
                ar[i*4+0] = t.x; ar[i*4+1] = t.y; ar[i*4+2] = t.z; ar[i*4+3] = t.w;
            }
            #pragma unroll
            for (int j = 0; j < TN / 4; j++) {
                float4 t = *(const float4*)&Bs[kk][tx * TN + j * 4];
                br[j*4+0] = t.x; br[j*4+1] = t.y; br[j*4+2] = t.z; br[j*4+3] = t.w;
            }
            #pragma unroll
            for (int i = 0; i < TM; i++)
                #pragma unroll
                for (int j = 0; j < TN; j++)
                    acc[i][j] += ar[i] * br[j];
        }
        __syncthreads();
    }
    #pragma unroll
    for (int i = 0; i < TM; i++) {
        int gm = m0 + ty * TM + i; if (gm >= M) continue;
        #pragma unroll
        for (int j = 0; j < TN; j++) {
            int gn = n0 + tx * TN + j; if (gn >= N) continue;
            float v = acc[i][j];
            if (epi >= 1) v += bias[gn];
            if (epi == 2)      v = 0.5f * v * (1.0f + erff(v * 0.70710678118654752f));
            else if (epi == 3) v += res[(long long)gm * ldc + gn];
            C[(long long)gm * ldc + gn] = v;
        }
    }
}

// ---------------- fused per-patch MHA (L=32, 4 heads, d=128) ----------------
#define PA_ST 129
__global__ void patch_attn_kernel(const float* __restrict__ qkv, const int* __restrict__ lengths,
                                  float* __restrict__ out){
    __shared__ float buf0[32 * PA_ST];
    __shared__ float buf1[32 * PA_ST];
    __shared__ float a[32 * 33];
    const int p = blockIdx.x, h = blockIdx.y;
    const int tid = threadIdx.x;
    const int len = lengths[p];
    const float scale = 0.0883883476483184406f;   // 1/sqrt(128)
    const float* base = qkv + (long long)p * 32 * 1536 + h * 128;

    // load q (scaled) and k
    #pragma unroll 8
    for (int i = 0; i < 32; i++) {
        int idx = i * 128 + tid; int l = idx >> 7, e = idx & 127;
        buf0[l * PA_ST + e] = base[l * 1536 + e] * scale;
        buf1[l * PA_ST + e] = base[l * 1536 + 512 + e];
    }
    __syncthreads();
    // scores (32x32), key mask
    #pragma unroll
    for (int i = 0; i < 8; i++) {
        int idx = i * 128 + tid; int row = idx >> 5, col = idx & 31;
        float d = 0.f;
        #pragma unroll 16
        for (int kk = 0; kk < 128; kk++)
            d += buf0[row * PA_ST + kk] * buf1[col * PA_ST + kk];
        a[row * 33 + col] = (col < len) ? d : -1e9f;
    }
    __syncthreads();
    // per-row softmax
    if (tid < 32) {
        float m = -1e30f;
        #pragma unroll
        for (int c = 0; c < 32; c++) m = fmaxf(m, a[tid * 33 + c]);
        float s = 0.f;
        #pragma unroll
        for (int c = 0; c < 32; c++) { float e = expf(a[tid * 33 + c] - m); a[tid * 33 + c] = e; s += e; }
        float inv = 1.f / s;
        #pragma unroll
        for (int c = 0; c < 32; c++) a[tid * 33 + c] *= inv;
    }
    __syncthreads();
    // load v over q
    #pragma unroll 8
    for (int i = 0; i < 32; i++) {
        int idx = i * 128 + tid; int l = idx >> 7, e = idx & 127;
        buf0[l * PA_ST + e] = base[l * 1536 + 1024 + e];
    }
    __syncthreads();
    // O = A @ V : thread (row=lane, warp handles 32-col slab)
    const int row = tid & 31, eb = (tid >> 5) * 32;
    float acc[32];
    #pragma unroll
    for (int e = 0; e < 32; e++) acc[e] = 0.f;
    for (int j = 0; j < 32; j++) {
        float aj = a[row * 33 + j];
        #pragma unroll
        for (int e = 0; e < 32; e++) acc[e] += aj * buf0[j * PA_ST + eb + e];
    }
    #pragma unroll
    for (int e = 0; e < 32; e++) buf1[row * PA_ST + eb + e] = acc[e];
    __syncthreads();
    float* o = out + (long long)p * 32 * 512 + h * 128;
    #pragma unroll 8
    for (int i = 0; i < 32; i++) {
        int idx = i * 128 + tid; int l = idx >> 7, e = idx & 127;
        o[l * 512 + e] = buf1[l * PA_ST + e];
    }
}

// ---------------- masked mean over bytes ----------------
__global__ void mean_kernel(const float* __restrict__ x, const int* __restrict__ lengths,
                            float* __restrict__ out){
    int p = blockIdx.x, e = threadIdx.x;   // blockDim = 512
    int len = lengths[p];
    float s = 0.f;
    for (int l = 0; l < len; l++) s += x[((long long)p * 32 + l) * 512 + e];
    out[p * 512 + e] = s * (1.f / (float)len);
}

// ---------------- layer norm (rows of 768) ----------------
__global__ void ln_kernel(const float* __restrict__ x, const float* __restrict__ w,
                          const float* __restrict__ b, float* __restrict__ y){
    int row = blockIdx.x, tid = threadIdx.x;   // blockDim = 256
    const float* xr = x + (long long)row * DD;
    float v0 = xr[tid], v1 = xr[tid + 256], v2 = xr[tid + 512];
    float mu = blockSum(v0 + v1 + v2) * (1.f / (float)DD);
    float d0 = v0 - mu, d1 = v1 - mu, d2 = v2 - mu;
    float var = blockSum(d0 * d0 + d1 * d1 + d2 * d2) * (1.f / (float)DD);
    float rstd = rsqrtf(var + 1e-5f);
    float* yr = y + (long long)row * DD;
    yr[tid]       = d0 * rstd * w[tid]       + b[tid];
    yr[tid + 256] = d1 * rstd * w[tid + 256] + b[tid + 256];
    yr[tid + 512] = d2 * rstd * w[tid + 512] + b[tid + 512];
}

// ---------------- row softmax (1024 cols, with scale) ----------------
__global__ void softmax_kernel(float* __restrict__ s, float scale){
    float* r = s + (long long)blockIdx.x * 1024;
    int tid = threadIdx.x;   // 256
    float v[4];
    float m = -1e30f;
    #pragma unroll
    for (int i = 0; i < 4; i++) { v[i] = r[tid + i * 256]; m = fmaxf(m, v[i]); }
    m = blockMax(m);
    float sum = 0.f;
    #pragma unroll
    for (int i = 0; i < 4; i++) { v[i] = expf((v[i] - m) * scale); sum += v[i]; }
    sum = blockSum(sum);
    float inv = 1.f / sum;
    #pragma unroll
    for (int i = 0; i < 4; i++) r[tid + i * 256] = v[i] * inv;
}

// ---------------- host-side launch helpers ----------------
static void gemm128(const float* A, const float* B, const float* bias, const float* res, float* C,
                    int M, int N, int K, int lda_m, int lda_k, int ldb_n, int ldb_k, int ldc,
                    long long bA, long long bB, long long bC, int batch, int epi){
    dim3 grid((N + 127) / 128, (M + 127) / 128, batch);
    gemm_kernel<128,128,16,8,8><<<grid, 256>>>(A,B,bias,res,C,M,N,K,lda_m,lda_k,ldb_n,ldb_k,ldc,bA,bB,bC,epi);
}
static void gemm64(const float* A, const float* B, const float* bias, const float* res, float* C,
                   int M, int N, int K, int lda_m, int lda_k, int ldb_n, int ldb_k, int ldc,
                   long long bA, long long bB, long long bC, int batch, int epi){
    dim3 grid((N + 63) / 64, (M + 63) / 64, batch);
    gemm_kernel<64,64,16,4,4><<<grid, 256>>>(A,B,bias,res,C,M,N,K,lda_m,lda_k,ldb_n,ldb_k,ldc,bA,bB,bC,epi);
}

extern "C" void kernel_launch(void* const* d_in, const int* in_sizes, int n_in,
                              void* d_out, int out_size){
    const int*   tokens   = (const int*)  d_in[0];
    const int*   lengths  = (const int*)  d_in[1];
    const float* byte_emb = (const float*)d_in[2];
    const float* lpos     = (const float*)d_in[3];
    const float* ppos     = (const float*)d_in[4];
    const float* pa_qkv_w = (const float*)d_in[5];
    const float* pa_qkv_b = (const float*)d_in[6];
    const float* pa_out_w = (const float*)d_in[7];
    const float* pa_out_b = (const float*)d_in[8];
    const float* proj_w   = (const float*)d_in[9];
    const float* proj_b   = (const float*)d_in[10];
    const float* lw_qkv   = (const float*)d_in[11];
    const float* lb_qkv   = (const float*)d_in[12];
    const float* lw_out   = (const float*)d_in[13];
    const float* lb_out   = (const float*)d_in[14];
    const float* ln1w     = (const float*)d_in[15];
    const float* ln1b     = (const float*)d_in[16];
    const float* ln2w     = (const float*)d_in[17];
    const float* ln2b     = (const float*)d_in[18];
    const float* ffw1     = (const float*)d_in[19];
    const float* ffb1     = (const float*)d_in[20];
    const float* ffw2     = (const float*)d_in[21];
    const float* ffb2     = (const float*)d_in[22];
    const float* lnfw     = (const float*)d_in[23];
    const float* lnfb     = (const float*)d_in[24];
    float* out = (float*)d_out;

    float *emb, *qkv, *attn, *attnout, *patch, *h, *hn, *qkvt, *scores, *attnt, *ff;
    cudaGetSymbolAddress((void**)&emb,     g_emb);
    cudaGetSymbolAddress((void**)&qkv,     g_qkv);
    cudaGetSymbolAddress((void**)&attn,    g_attn);
    cudaGetSymbolAddress((void**)&attnout, g_attnout);
    cudaGetSymbolAddress((void**)&patch,   g_patch);
    cudaGetSymbolAddress((void**)&h,       g_h);
    cudaGetSymbolAddress((void**)&hn,      g_hn);
    cudaGetSymbolAddress((void**)&qkvt,    g_qkvt);
    cudaGetSymbolAddress((void**)&scores,  g_scores);
    cudaGetSymbolAddress((void**)&attnt,   g_attnt);
    cudaGetSymbolAddress((void**)&ff,      g_ff);

    // 1) byte embedding + mask
    embed_kernel<<<(TT * EE) / 256, 256>>>(tokens, lengths, byte_emb, lpos, emb);

    // 2) patch-attention QKV:  [32768,512] @ [1536,512]^T + b
    gemm128(emb, pa_qkv_w, pa_qkv_b, nullptr, qkv,
            TT, 3*EE, EE, EE, 1, EE, 1, 3*EE, 0, 0, 0, 1, 1);

    // 3) fused per-patch attention
    patch_attn_kernel<<<dim3(PP, 4), 128>>>(qkv, lengths, attn);

    // 4) patch out-proj: [32768,512] @ [512,512]^T + b
    gemm128(attn, pa_out_w, pa_out_b, nullptr, attnout,
            TT, EE, EE, EE, 1, EE, 1, EE, 0, 0, 0, 1, 1);

    // 5) masked mean -> [1024,512]
    mean_kernel<<<PP, 512>>>(attnout, lengths, patch);

    // 6) project to D + patch positions: [1024,512]@[768,512]^T + b + ppos
    gemm64(patch, proj_w, proj_b, ppos, h,
           PP, DD, EE, EE, 1, EE, 1, DD, 0, 0, 0, 1, 3);

    const float tr_scale = 0.1020620726159657588f;   // 1/sqrt(96)

    for (int i = 0; i < NLAY; i++) {
        const float* qkv_w = lw_qkv + (size_t)i * 3 * DD * DD;
        const float* qkv_b = lb_qkv + (size_t)i * 3 * DD;
        const float* out_w = lw_out + (size_t)i * DD * DD;
        const float* out_b = lb_out + (size_t)i * DD;
        const float* f1w   = ffw1  + (size_t)i * FFD * DD;
        const float* f1b   = ffb1  + (size_t)i * FFD;
        const float* f2w   = ffw2  + (size_t)i * DD * FFD;
        const float* f2b   = ffb2  + (size_t)i * DD;

        // LN1
        ln_kernel<<<PP, 256>>>(h, ln1w + (size_t)i * DD, ln1b + (size_t)i * DD, hn);
        // QKV: [1024,768]@[2304,768]^T + b
        gemm64(hn, qkv_w, qkv_b, nullptr, qkvt,
               PP, 3*DD, DD, DD, 1, DD, 1, 3*DD, 0, 0, 0, 1, 1);
        // scores per head: Q[1024,96] @ K[1024,96]^T  (batched over 8 heads)
        gemm128(qkvt, qkvt + DD, nullptr, nullptr, scores,
                PP, PP, 96, 3*DD, 1, 3*DD, 1, PP,
                96, 96, (long long)PP * PP, 8, 0);
        // softmax rows (scale folded in)
        softmax_kernel<<<8 * PP, 256>>>(scores, tr_scale);
        // AV: A[1024,1024] @ V[1024,96]  (B[n][k] = v[k*2304 + n])
        gemm64(scores, qkvt + 2*DD, nullptr, nullptr, attnt,
               PP, 96, PP, PP, 1, 1, 3*DD, DD,
               (long long)PP * PP, 96, 96, 8, 0);
        // out-proj + residual into h
        gemm64(attnt, out_w, out_b, h, h,
               PP, DD, DD, DD, 1, DD, 1, DD, 0, 0, 0, 1, 3);
        // LN2
        ln_kernel<<<PP, 256>>>(h, ln2w + (size_t)i * DD, ln2b + (size_t)i * DD, hn);
        // FF1 + exact gelu
        gemm128(hn, f1w, f1b, nullptr, ff,
                PP, FFD, DD, DD, 1, DD, 1, FFD, 0, 0, 0, 1, 2);
        // FF2 + residual into h
        gemm64(ff, f2w, f2b, h, h,
               PP, DD, FFD, FFD, 1, FFD, 1, DD, 0, 0, 0, 1, 3);
    }

    // final LN -> output
    ln_kernel<<<PP, 256>>>(h, lnfw, lnfb, out);
}

// round 2
// speedup vs baseline: 1.2072x; 1.2072x over previous
#include <cuda_runtime.h>
#include <math.h>
#include <stdint.h>

#define PP 1024
#define LL 32
#define EE 512
#define DD 768
#define NLAY 6
#define FFD 3072
#define TT (PP*LL)   // 32768 byte tokens

// ---------------- scratch (static device globals; no runtime alloc) ----------------
__device__ float g_emb[TT*EE];
__device__ float g_qkv[TT*3*EE];
__device__ float g_attn[TT*EE];
__device__ float g_attnout[TT*EE];
__device__ float g_patch[PP*EE];
__device__ float g_h[PP*DD];
__device__ float g_hn[PP*DD];
__device__ float g_qkvt[PP*3*DD];
__device__ float g_scores[8*PP*PP];
__device__ float g_attnt[PP*DD];
__device__ float g_ff[PP*FFD];

// ---------------- block reductions ----------------
__device__ __forceinline__ float blockSum(float v){
    __shared__ float sh[32];
    int lane = threadIdx.x & 31, wid = threadIdx.x >> 5, nw = blockDim.x >> 5;
    #pragma unroll
    for (int o = 16; o; o >>= 1) v += __shfl_xor_sync(0xffffffffu, v, o);
    if (lane == 0) sh[wid] = v;
    __syncthreads();
    float t = (lane < nw) ? sh[lane] : 0.f;
    #pragma unroll
    for (int o = 16; o; o >>= 1) t += __shfl_xor_sync(0xffffffffu, t, o);
    __syncthreads();
    return t;
}
__device__ __forceinline__ float blockMax(float v){
    __shared__ float sh[32];
    int lane = threadIdx.x & 31, wid = threadIdx.x >> 5, nw = blockDim.x >> 5;
    #pragma unroll
    for (int o = 16; o; o >>= 1) v = fmaxf(v, __shfl_xor_sync(0xffffffffu, v, o));
    if (lane == 0) sh[wid] = v;
    __syncthreads();
    float t = (lane < nw) ? sh[lane] : -1e30f;
    #pragma unroll
    for (int o = 16; o; o >>= 1) t = fmaxf(t, __shfl_xor_sync(0xffffffffu, t, o));
    __syncthreads();
    return t;
}

// ---------------- embedding + mask ----------------
__global__ void embed_kernel(const int* __restrict__ tokens, const int* __restrict__ lengths,
                             const float* __restrict__ bemb, const float* __restrict__ lpos,
                             float* __restrict__ out){
    int idx = blockIdx.x * blockDim.x + threadIdx.x;
    if (idx >= TT * EE) return;
    int e = idx & (EE - 1);
    int t = idx >> 9;
    int l = t & (LL - 1);
    int p = t >> 5;
    float v = 0.f;
    if (l < lengths[p]) {
        int tok = tokens[t];
        v = bemb[tok * EE + e] + lpos[l * EE + e];
    }
    out[idx] = v;
}

// ---------------- TF32 tensor-core helpers ----------------
__device__ __forceinline__ uint32_t cvt_tf32(float x){
    uint32_t r; asm("cvt.rna.tf32.f32 %0, %1;" : "=r"(r) : "f"(x)); return r;
}
__device__ __forceinline__ void split_tf32(float x, uint32_t &hi, uint32_t &lo){
    hi = cvt_tf32(x);
    lo = cvt_tf32(x - __uint_as_float(hi));
}
__device__ __forceinline__ void mma_m16n8k8(float* c, const uint32_t* a, const uint32_t* b){
    asm("mma.sync.aligned.m16n8k8.row.col.f32.tf32.tf32.f32 "
        "{%0,%1,%2,%3}, {%4,%5,%6,%7}, {%8,%9}, {%0,%1,%2,%3};"
        : "+f"(c[0]), "+f"(c[1]), "+f"(c[2]), "+f"(c[3])
        : "r"(a[0]), "r"(a[1]), "r"(a[2]), "r"(a[3]), "r"(b[0]), "r"(b[1]));
}

// ---------------- 3xTF32 tensor-core GEMM: C = A[M,K] * B[N,K]^T (+epi) ----------------
// epi: 0 none, 1 bias, 2 bias+gelu(exact), 3 bias+residual
template<int BM, int BN, int BK, int WARPS_M, int WARPS_N>
__global__ void __launch_bounds__(WARPS_M*WARPS_N*32)
gemm_tf32_kernel(const float* __restrict__ A, const float* __restrict__ B,
                 const float* __restrict__ bias, const float* __restrict__ res,
                 float* __restrict__ C,
                 int M, int N, int K,
                 int lda_m, int lda_k, int ldb_n, int ldb_k, int ldc,
                 long long bA, long long bB, long long bC, int epi){
    constexpr int THREADS = WARPS_M * WARPS_N * 32;
    constexpr int WM = BM / WARPS_M;          // rows per warp
    constexpr int WN = BN / WARPS_N;          // cols per warp
    constexpr int MT = WM / 16;               // m16 tiles per warp
    constexpr int NTT = WN / 8;               // n8 tiles per warp
    constexpr int PAD = 8;
    __shared__ float As[BK][BM + PAD];
    __shared__ float Bs[BK][BN + PAD];

    const int tid = threadIdx.x;
    A += (long long)blockIdx.z * bA;
    B += (long long)blockIdx.z * bB;
    C += (long long)blockIdx.z * bC;
    const int m0 = blockIdx.y * BM, n0 = blockIdx.x * BN;

    const int w = tid >> 5, lane = tid & 31;
    const int wm = (w / WARPS_N) * WM, wn = (w % WARPS_N) * WN;
    const int g = lane >> 2, t4 = lane & 3;

    float acc[MT][NTT][4];
    #pragma unroll
    for (int i = 0; i < MT; i++)
        #pragma unroll
        for (int j = 0; j < NTT; j++)
            #pragma unroll
            for (int r = 0; r < 4; r++) acc[i][j][r] = 0.f;

    constexpr int AELEM = BM * BK / THREADS;
    constexpr int BELEM = BN * BK / THREADS;

    for (int k0 = 0; k0 < K; k0 += BK) {
        if (lda_k == 1) {
            #pragma unroll
            for (int i = 0; i < AELEM; i++) {
                int idx = i * THREADS + tid; int m = idx / BK, kk = idx % BK;
                int gm = m0 + m, gk = k0 + kk;
                As[kk][m] = (gm < M && gk < K) ? A[(long long)gm * lda_m + gk] : 0.f;
            }
        } else {
            #pragma unroll
            for (int i = 0; i < AELEM; i++) {
                int idx = i * THREADS + tid; int m = idx % BM, kk = idx / BM;
                int gm = m0 + m, gk = k0 + kk;
                As[kk][m] = (gm < M && gk < K) ? A[(long long)gm * lda_m + (long long)gk * lda_k] : 0.f;
            }
        }
        if (ldb_k == 1) {
            #pragma unroll
            for (int i = 0; i < BELEM; i++) {
                int idx = i * THREADS + tid; int n = idx / BK, kk = idx % BK;
                int gn = n0 + n, gk = k0 + kk;
                Bs[kk][n] = (gn < N && gk < K) ? B[(long long)gn * ldb_n + gk] : 0.f;
            }
        } else {
            #pragma unroll
            for (int i = 0; i < BELEM; i++) {
                int idx = i * THREADS + tid; int n = idx % BN, kk = idx / BN;
                int gn = n0 + n, gk = k0 + kk;
                Bs[kk][n] = (gn < N && gk < K) ? B[(long long)gn * ldb_n + (long long)gk * ldb_k] : 0.f;
            }
        }
        __syncthreads();

        #pragma unroll
        for (int kc = 0; kc < BK / 8; kc++) {
            uint32_t ah[MT][4], al[MT][4], bh[NTT][2], bl[NTT][2];
            const int ka = kc * 8 + t4, kb = ka + 4;
            #pragma unroll
            for (int i = 0; i < MT; i++) {
                int r0 = wm + i * 16 + g;
                split_tf32(As[ka][r0],     ah[i][0], al[i][0]);
                split_tf32(As[ka][r0 + 8], ah[i][1], al[i][1]);
                split_tf32(As[kb][r0],     ah[i][2], al[i][2]);
                split_tf32(As[kb][r0 + 8], ah[i][3], al[i][3]);
            }
            #pragma unroll
            for (int j = 0; j < NTT; j++) {
                int n = wn + j * 8 + g;
                split_tf32(Bs[ka][n], bh[j][0], bl[j][0]);
                split_tf32(Bs[kb][n], bh[j][1], bl[j][1]);
            }
            #pragma unroll
            for (int i = 0; i < MT; i++)
                #pragma unroll
                for (int j = 0; j < NTT; j++) {
                    mma_m16n8k8(acc[i][j], ah[i], bh[j]);   // hi*hi
                    mma_m16n8k8(acc[i][j], ah[i], bl[j]);   // hi*lo
                    mma_m16n8k8(acc[i][j], al[i], bh[j]);   // lo*hi
                }
        }
        __syncthreads();
    }

    // epilogue: c0->(g, 2t), c1->(g, 2t+1), c2->(g+8, 2t), c3->(g+8, 2t+1)
    #pragma unroll
    for (int i = 0; i < MT; i++) {
        #pragma unroll
        for (int j = 0; j < NTT; j++) {
            #pragma unroll
            for (int r = 0; r < 4; r++) {
                int gm = m0 + wm + i * 16 + g + (r >= 2 ? 8 : 0);
                int gn = n0 + wn + j * 8 + 2 * t4 + (r & 1);
                if (gm >= M || gn >= N) continue;
                float v = acc[i][j][r];
                if (epi >= 1) v += bias[gn];
                if (epi == 2)      v = 0.5f * v * (1.0f + erff(v * 0.70710678118654752f));
                else if (epi == 3) v += res[(long long)gm * ldc + gn];
                C[(long long)gm * ldc + gn] = v;
            }
        }
    }
}

// ---------------- fused per-patch MHA (L=32, 4 heads, d=128) ----------------
#define PA_ST 129
__global__ void patch_attn_kernel(const float* __restrict__ qkv, const int* __restrict__ lengths,
                                  float* __restrict__ out){
    __shared__ float buf0[32 * PA_ST];
    __shared__ float buf1[32 * PA_ST];
    __shared__ float a[32 * 33];
    const int p = blockIdx.x, h = blockIdx.y;
    const int tid = threadIdx.x;
    const int len = lengths[p];
    const float scale = 0.0883883476483184406f;   // 1/sqrt(128)
    const float* base = qkv + (long long)p * 32 * 1536 + h * 128;

    #pragma unroll 8
    for (int i = 0; i < 32; i++) {
        int idx = i * 128 + tid; int l = idx >> 7, e = idx & 127;
        buf0[l * PA_ST + e] = base[l * 1536 + e] * scale;
        buf1[l * PA_ST + e] = base[l * 1536 + 512 + e];
    }
    __syncthreads();
    #pragma unroll
    for (int i = 0; i < 8; i++) {
        int idx = i * 128 + tid; int row = idx >> 5, col = idx & 31;
        float d = 0.f;
        #pragma unroll 16
        for (int kk = 0; kk < 128; kk++)
            d += buf0[row * PA_ST + kk] * buf1[col * PA_ST + kk];
        a[row * 33 + col] = (col < len) ? d : -1e9f;
    }
    __syncthreads();
    if (tid < 32) {
        float m = -1e30f;
        #pragma unroll
        for (int c = 0; c < 32; c++) m = fmaxf(m, a[tid * 33 + c]);
        float s = 0.f;
        #pragma unroll
        for (int c = 0; c < 32; c++) { float e = expf(a[tid * 33 + c] - m); a[tid * 33 + c] = e; s += e; }
        float inv = 1.f / s;
        #pragma unroll
        for (int c = 0; c < 32; c++) a[tid * 33 + c] *= inv;
    }
    __syncthreads();
    #pragma unroll 8
    for (int i = 0; i < 32; i++) {
        int idx = i * 128 + tid; int l = idx >> 7, e = idx & 127;
        buf0[l * PA_ST + e] = base[l * 1536 + 1024 + e];
    }
    __syncthreads();
    const int row = tid & 31, eb = (tid >> 5) * 32;
    float acc[32];
    #pragma unroll
    for (int e = 0; e < 32; e++) acc[e] = 0.f;
    for (int j = 0; j < 32; j++) {
        float aj = a[row * 33 + j];
        #pragma unroll
        for (int e = 0; e < 32; e++) acc[e] += aj * buf0[j * PA_ST + eb + e];
    }
    #pragma unroll
    for (int e = 0; e < 32; e++) buf1[row * PA_ST + eb + e] = acc[e];
    __syncthreads();
    float* o = out + (long long)p * 32 * 512 + h * 128;
    #pragma unroll 8
    for (int i = 0; i < 32; i++) {
        int idx = i * 128 + tid; int l = idx >> 7, e = idx & 127;
        o[l * 512 + e] = buf1[l * PA_ST + e];
    }
}

// ---------------- masked mean over bytes ----------------
__global__ void mean_kernel(const float* __restrict__ x, const int* __restrict__ lengths,
                            float* __restrict__ out){
    int p = blockIdx.x, e = threadIdx.x;
    int len = lengths[p];
    float s = 0.f;
    for (int l = 0; l < len; l++) s += x[((long long)p * 32 + l) * 512 + e];
    out[p * 512 + e] = s * (1.f / (float)len);
}

// ---------------- layer norm (rows of 768) ----------------
__global__ void ln_kernel(const float* __restrict__ x, const float* __restrict__ w,
                          const float* __restrict__ b, float* __restrict__ y){
    int row = blockIdx.x, tid = threadIdx.x;
    const float* xr = x + (long long)row * DD;
    float v0 = xr[tid], v1 = xr[tid + 256], v2 = xr[tid + 512];
    float mu = blockSum(v0 + v1 + v2) * (1.f / (float)DD);
    float d0 = v0 - mu, d1 = v1 - mu, d2 = v2 - mu;
    float var = blockSum(d0 * d0 + d1 * d1 + d2 * d2) * (1.f / (float)DD);
    float rstd = rsqrtf(var + 1e-5f);
    float* yr = y + (long long)row * DD;
    yr[tid]       = d0 * rstd * w[tid]       + b[tid];
    yr[tid + 256] = d1 * rstd * w[tid + 256] + b[tid + 256];
    yr[tid + 512] = d2 * rstd * w[tid + 512] + b[tid + 512];
}

// ---------------- row softmax (1024 cols, with scale) ----------------
__global__ void softmax_kernel(float* __restrict__ s, float scale){
    float* r = s + (long long)blockIdx.x * 1024;
    int tid = threadIdx.x;
    float v[4];
    float m = -1e30f;
    #pragma unroll
    for (int i = 0; i < 4; i++) { v[i] = r[tid + i * 256]; m = fmaxf(m, v[i]); }
    m = blockMax(m);
    float sum = 0.f;
    #pragma unroll
    for (int i = 0; i < 4; i++) { v[i] = expf((v[i] - m) * scale); sum += v[i]; }
    sum = blockSum(sum);
    float inv = 1.f / sum;
    #pragma unroll
    for (int i = 0; i < 4; i++) r[tid + i * 256] = v[i] * inv;
}

// ---------------- host-side launch helpers ----------------
static void gemm128(const float* A, const float* B, const float* bias, const float* res, float* C,
                    int M, int N, int K, int lda_m, int lda_k, int ldb_n, int ldb_k, int ldc,
                    long long bA, long long bB, long long bC, int batch, int epi){
    dim3 grid((N + 127) / 128, (M + 127) / 128, batch);
    gemm_tf32_kernel<128,128,32,2,4><<<grid, 256>>>(A,B,bias,res,C,M,N,K,lda_m,lda_k,ldb_n,ldb_k,ldc,bA,bB,bC,epi);
}
static void gemm64(const float* A, const float* B, const float* bias, const float* res, float* C,
                   int M, int N, int K, int lda_m, int lda_k, int ldb_n, int ldb_k, int ldc,
                   long long bA, long long bB, long long bC, int batch, int epi){
    dim3 grid((N + 63) / 64, (M + 63) / 64, batch);
    gemm_tf32_kernel<64,64,32,2,2><<<grid, 128>>>(A,B,bias,res,C,M,N,K,lda_m,lda_k,ldb_n,ldb_k,ldc,bA,bB,bC,epi);
}

extern "C" void kernel_launch(void* const* d_in, const int* in_sizes, int n_in,
                              void* d_out, int out_size){
    const int*   tokens   = (const int*)  d_in[0];
    const int*   lengths  = (const int*)  d_in[1];
    const float* byte_emb = (const float*)d_in[2];
    const float* lpos     = (const float*)d_in[3];
    const float* ppos     = (const float*)d_in[4];
    const float* pa_qkv_w = (const float*)d_in[5];
    const float* pa_qkv_b = (const float*)d_in[6];
    const float* pa_out_w = (const float*)d_in[7];
    const float* pa_out_b = (const float*)d_in[8];
    const float* proj_w   = (const float*)d_in[9];
    const float* proj_b   = (const float*)d_in[10];
    const float* lw_qkv   = (const float*)d_in[11];
    const float* lb_qkv   = (const float*)d_in[12];
    const float* lw_out   = (const float*)d_in[13];
    const float* lb_out   = (const float*)d_in[14];
    const float* ln1w     = (const float*)d_in[15];
    const float* ln1b     = (const float*)d_in[16];
    const float* ln2w     = (const float*)d_in[17];
    const float* ln2b     = (const float*)d_in[18];
    const float* ffw1     = (const float*)d_in[19];
    const float* ffb1     = (const float*)d_in[20];
    const float* ffw2     = (const float*)d_in[21];
    const float* ffb2     = (const float*)d_in[22];
    const float* lnfw     = (const float*)d_in[23];
    const float* lnfb     = (const float*)d_in[24];
    float* out = (float*)d_out;

    float *emb, *qkv, *attn, *attnout, *patch, *h, *hn, *qkvt, *scores, *attnt, *ff;
    cudaGetSymbolAddress((void**)&emb,     g_emb);
    cudaGetSymbolAddress((void**)&qkv,     g_qkv);
    cudaGetSymbolAddress((void**)&attn,    g_attn);
    cudaGetSymbolAddress((void**)&attnout, g_attnout);
    cudaGetSymbolAddress((void**)&patch,   g_patch);
    cudaGetSymbolAddress((void**)&h,       g_h);
    cudaGetSymbolAddress((void**)&hn,      g_hn);
    cudaGetSymbolAddress((void**)&qkvt,    g_qkvt);
    cudaGetSymbolAddress((void**)&scores,  g_scores);
    cudaGetSymbolAddress((void**)&attnt,   g_attnt);
    cudaGetSymbolAddress((void**)&ff,      g_ff);

    // 1) byte embedding + mask
    embed_kernel<<<(TT * EE) / 256, 256>>>(tokens, lengths, byte_emb, lpos, emb);

    // 2) patch-attention QKV:  [32768,512] @ [1536,512]^T + b
    gemm128(emb, pa_qkv_w, pa_qkv_b, nullptr, qkv,
            TT, 3*EE, EE, EE, 1, EE, 1, 3*EE, 0, 0, 0, 1, 1);

    // 3) fused per-patch attention
    patch_attn_kernel<<<dim3(PP, 4), 128>>>(qkv, lengths, attn);

    // 4) patch out-proj: [32768,512] @ [512,512]^T + b
    gemm128(attn, pa_out_w, pa_out_b, nullptr, attnout,
            TT, EE, EE, EE, 1, EE, 1, EE, 0, 0, 0, 1, 1);

    // 5) masked mean -> [1024,512]
    mean_kernel<<<PP, 512>>>(attnout, lengths, patch);

    // 6) project to D + patch positions
    gemm64(patch, proj_w, proj_b, ppos, h,
           PP, DD, EE, EE, 1, EE, 1, DD, 0, 0, 0, 1, 3);

    const float tr_scale = 0.1020620726159657588f;   // 1/sqrt(96)

    for (int i = 0; i < NLAY; i++) {
        const float* qkv_w = lw_qkv + (size_t)i * 3 * DD * DD;
        const float* qkv_b = lb_qkv + (size_t)i * 3 * DD;
        const float* out_w = lw_out + (size_t)i * DD * DD;
        const float* out_b = lb_out + (size_t)i * DD;
        const float* f1w   = ffw1  + (size_t)i * FFD * DD;
        const float* f1b   = ffb1  + (size_t)i * FFD;
        const float* f2w   = ffw2  + (size_t)i * DD * FFD;
        const float* f2b   = ffb2  + (size_t)i * DD;

        // LN1
        ln_kernel<<<PP, 256>>>(h, ln1w + (size_t)i * DD, ln1b + (size_t)i * DD, hn);
        // QKV: [1024,768]@[2304,768]^T + b  (144 blocks of 128x128, single wave)
        gemm128(hn, qkv_w, qkv_b, nullptr, qkvt,
                PP, 3*DD, DD, DD, 1, DD, 1, 3*DD, 0, 0, 0, 1, 1);
        // scores per head: Q[1024,96] @ K[1024,96]^T  (batched over 8 heads)
        gemm128(qkvt, qkvt + DD, nullptr, nullptr, scores,
                PP, PP, 96, 3*DD, 1, 3*DD, 1, PP,
                96, 96, (long long)PP * PP, 8, 0);
        // softmax rows (scale folded in)
        softmax_kernel<<<8 * PP, 256>>>(scores, tr_scale);
        // AV: A[1024,1024] @ V[1024,96]
        gemm64(scores, qkvt + 2*DD, nullptr, nullptr, attnt,
               PP, 96, PP, PP, 1, 1, 3*DD, DD,
               (long long)PP * PP, 96, 96, 8, 0);
        // out-proj + residual into h
        gemm64(attnt, out_w, out_b, h, h,
               PP, DD, DD, DD, 1, DD, 1, DD, 0, 0, 0, 1, 3);
        // LN2
        ln_kernel<<<PP, 256>>>(h, ln2w + (size_t)i * DD, ln2b + (size_t)i * DD, hn);
        // FF1 + exact gelu  (192 blocks of 128x128)
        gemm128(hn, f1w, f1b, nullptr, ff,
                PP, FFD, DD, DD, 1, DD, 1, FFD, 0, 0, 0, 1, 2);
        // FF2 + residual into h  (192 blocks of 64x64)
        gemm64(ff, f2w, f2b, h, h,
               PP, DD, FFD, FFD, 1, FFD, 1, DD, 0, 0, 0, 1, 3);
    }

    // final LN -> output
    ln_kernel<<<PP, 256>>>(h, lnfw, lnfb, out);
}